// round 1
// baseline (speedup 1.0000x reference)
#include <cuda_runtime.h>

#define SEQ   512
#define NC    9
#define NEGV  (-10000.0f)
#define TPB   32
#define NBLK  256           // 8192 / 32
#define LOG2E 1.4426950408889634f
#define LN2   0.6931471805599453f

__device__ float g_partials[NBLK];

// One fast forward step in scaled exp-domain + fused gold accumulation.
__device__ __forceinline__ void fast_step(
    const float* __restrict__ em_row, int t,
    const float (&ev)[NC], int l, int m,
    float (&q)[NC], float& c2, float& gold, int& prev, int& cnt,
    const float (&ET)[NC * NC], const float* __restrict__ Ts)
{
    float E[NC];
#pragma unroll
    for (int j = 0; j < NC; j++) E[j] = __expf(ev[j]);

    float r[NC];
#pragma unroll
    for (int j = 0; j < NC; j++) {
        float acc = q[0] * ET[0 * NC + j];
#pragma unroll
        for (int i = 1; i < NC; i++) acc = fmaf(q[i], ET[i * NC + j], acc);
        r[j] = acc * E[j];
    }

    float M = r[0];
#pragma unroll
    for (int j = 1; j < NC; j++) M = fmaxf(M, r[j]);
    M = fmaxf(M, 1e-37f);                 // safety floor (cannot trigger for t>=1 on this data)
    float inv = __fdividef(1.0f, M);

    bool u = (m != 0);
#pragma unroll
    for (int j = 0; j < NC; j++) q[j] = u ? (r[j] * inv) : q[j];
    c2 += u ? __log2f(M) : 0.0f;

    // gold: emission gather (L1 hit — same line loaded a few steps ago) + transition from smem
    float evl = __ldg(em_row + t * NC + l);
    gold += u ? (evl + Ts[prev * NC + l]) : 0.0f;
    cnt  += u ? 1 : 0;
    prev  = l;                            // labels_ext chain is unconditional on mask
}

__global__ void __launch_bounds__(TPB, 1)
crf_kernel(const float* __restrict__ emission,
           const float* __restrict__ transition,
           const int*   __restrict__ labels,
           const int*   __restrict__ mask)
{
    __shared__ float Ts[NC * NC];
    const int tid = threadIdx.x;
    for (int i = tid; i < NC * NC; i += TPB) Ts[i] = transition[i];
    __syncthreads();

    const int b = blockIdx.x * TPB + tid;
    const float* __restrict__ em_row = emission + (long long)b * SEQ * NC;
    const int*   __restrict__ lb_row = labels   + (long long)b * SEQ;
    const int*   __restrict__ mk_row = mask     + (long long)b * SEQ;

    // exp(T) held entirely in registers (all indexing static after full unroll)
    float ET[NC * NC];
#pragma unroll
    for (int i = 0; i < NC * NC; i++) ET[i] = __expf(Ts[i]);

    float q[NC];
    q[0] = 1.0f;
#pragma unroll
    for (int j = 1; j < NC; j++) q[j] = 0.0f;
    float c2 = 0.0f, gold = 0.0f;
    int prev = 0, cnt = 0;

    // ---- step 0: log-domain (robust to the all -1e4 START row that underflows exp-domain) ----
    {
        int l0 = __ldg(lb_row);
        int m0 = __ldg(mk_row);
        if (m0 != 0) {
            float n[NC];
#pragma unroll
            for (int j = 0; j < NC; j++) {
                float mx = Ts[0 * NC + j];                       // init_0 = 0
#pragma unroll
                for (int i = 1; i < NC; i++) mx = fmaxf(mx, NEGV + Ts[i * NC + j]);
                float ss = __expf(Ts[0 * NC + j] - mx);
#pragma unroll
                for (int i = 1; i < NC; i++) ss += __expf(NEGV + Ts[i * NC + j] - mx);
                n[j] = __ldg(em_row + j) + mx + __logf(ss);
            }
            float g = n[0];
#pragma unroll
            for (int j = 1; j < NC; j++) g = fmaxf(g, n[j]);
#pragma unroll
            for (int j = 0; j < NC; j++) q[j] = __expf(n[j] - g);
            c2 = g * LOG2E;
            gold = __ldg(em_row + l0) + Ts[0 * NC + l0];        // prev = START
            cnt = 1;
        }
        prev = l0;
    }

    // ---- steps 1..3: fast path, direct loads (pipeline warm-up) ----
#pragma unroll
    for (int t = 1; t < 4; t++) {
        float ev[NC];
#pragma unroll
        for (int j = 0; j < NC; j++) ev[j] = __ldg(em_row + t * NC + j);
        int l = __ldg(lb_row + t);
        int m = __ldg(mk_row + t);
        fast_step(em_row, t, ev, l, m, q, c2, gold, prev, cnt, ET, Ts);
    }

    // ---- steps 4..511: depth-4 register-pipelined fast path ----
    float eb[4][NC];
    int lbb[4], mkb[4];
#pragma unroll
    for (int d = 0; d < 4; d++) {
        int t = 4 + d;
#pragma unroll
        for (int j = 0; j < NC; j++) eb[d][j] = __ldg(em_row + t * NC + j);
        lbb[d] = __ldg(lb_row + t);
        mkb[d] = __ldg(mk_row + t);
    }

    for (int tb = 4; tb < SEQ; tb += 4) {
#pragma unroll
        for (int d = 0; d < 4; d++) {
            int t = tb + d;
            float ev[NC];
#pragma unroll
            for (int j = 0; j < NC; j++) ev[j] = eb[d][j];
            int l = lbb[d];
            int m = mkb[d];
            int tp = t + 4;
            tp = (tp < SEQ) ? tp : (SEQ - 1);                   // clamped prefetch, no branch
#pragma unroll
            for (int j = 0; j < NC; j++) eb[d][j] = __ldg(em_row + tp * NC + j);
            lbb[d] = __ldg(lb_row + tp);
            mkb[d] = __ldg(mk_row + tp);
            fast_step(em_row, t, ev, l, m, q, c2, gold, prev, cnt, ET, Ts);
        }
    }

    // ---- finalize: logZ = c2*ln2 + LSE_j( ln q_j + T[j, END] ) ----
    float f[NC];
#pragma unroll
    for (int j = 0; j < NC; j++) f[j] = __logf(q[j]) + Ts[j * NC + (NC - 1)];
    float mf = f[0];
#pragma unroll
    for (int j = 1; j < NC; j++) mf = fmaxf(mf, f[j]);
    float sum = 0.0f;
#pragma unroll
    for (int j = 0; j < NC; j++) sum += __expf(f[j] - mf);
    float logZ = c2 * LN2 + mf + __logf(sum);

    // gold: + T[last_label, END], last_label = labels_ext[lengths]
    int lastl = 0;
    if (cnt > 0) lastl = __ldg(lb_row + (cnt - 1));
    gold += Ts[lastl * NC + (NC - 1)];

    float diff = logZ - gold;
#pragma unroll
    for (int off = 16; off > 0; off >>= 1)
        diff += __shfl_down_sync(0xffffffffu, diff, off);
    if (tid == 0) g_partials[blockIdx.x] = diff;
}

__global__ void crf_reduce_kernel(float* __restrict__ out)
{
    __shared__ float sm[8];
    int t = threadIdx.x;                  // 256 threads
    float v = g_partials[t];
#pragma unroll
    for (int off = 16; off > 0; off >>= 1)
        v += __shfl_down_sync(0xffffffffu, v, off);
    if ((t & 31) == 0) sm[t >> 5] = v;
    __syncthreads();
    if (t < 8) {
        v = sm[t];
#pragma unroll
        for (int off = 4; off > 0; off >>= 1)
            v += __shfl_down_sync(0x000000ffu, v, off);
        if (t == 0) out[0] = v * (1.0f / 8192.0f);
    }
}

extern "C" void kernel_launch(void* const* d_in, const int* in_sizes, int n_in,
                              void* d_out, int out_size)
{
    (void)in_sizes; (void)n_in; (void)out_size;
    const float* emission   = (const float*)d_in[0];
    const float* transition = (const float*)d_in[1];
    const int*   labels     = (const int*)d_in[2];
    const int*   mask       = (const int*)d_in[3];
    float* out = (float*)d_out;

    crf_kernel<<<NBLK, TPB>>>(emission, transition, labels, mask);
    crf_reduce_kernel<<<1, 256>>>(out);
}